// round 1
// baseline (speedup 1.0000x reference)
#include <cuda_runtime.h>
#include <math.h>

// ---- Problem constants ----
#define B_  4
#define T_  1024
#define D_  1024
#define H_  16
#define L_  8
#define V_  50257
#define HD_ 64
#define NT_ (B_ * T_)          // 4096 token rows
#define EPS_ 1e-5f

// ---- Scratch (device globals; no allocation allowed) ----
__device__ float g_x  [NT_ * D_];        // residual stream        16 MB
__device__ float g_h  [NT_ * D_];        // layernorm output       16 MB
__device__ float g_qkv[NT_ * 3 * D_];    // qkv                    48 MB
__device__ float g_o  [NT_ * D_];        // attention output       16 MB
__device__ float g_ff [NT_ * 4 * D_];    // ff1 output             64 MB

// ---------------------------------------------------------------------------
// Embedding: x[b,t,:] = tok_emb[idx[b,t],:] + pos_emb[t,:]
// ---------------------------------------------------------------------------
__global__ void embed_kernel(const int* __restrict__ idx,
                             const float* __restrict__ tok,
                             const float* __restrict__ pos) {
    int row = blockIdx.x;                 // b*T + t
    int t   = row & (T_ - 1);
    int v   = idx[row];
    const float* tr = tok + (size_t)v * D_;
    const float* pr = pos + (size_t)t * D_;
    float* xr = g_x + (size_t)row * D_;
    for (int d = threadIdx.x; d < D_; d += blockDim.x)
        xr[d] = tr[d] + pr[d];
}

// ---------------------------------------------------------------------------
// LayerNorm: out = (x - mean) * rsqrt(var + eps) * s + b   (one block per row)
// ---------------------------------------------------------------------------
__global__ void ln_kernel(const float* __restrict__ in, float* __restrict__ out,
                          const float* __restrict__ scale,
                          const float* __restrict__ bias) {
    __shared__ float red[256];
    int row = blockIdx.x;
    int tid = threadIdx.x;
    const float* x = in + (size_t)row * D_;

    float s = 0.f;
    for (int d = tid; d < D_; d += 256) s += x[d];
    red[tid] = s; __syncthreads();
    for (int o = 128; o > 0; o >>= 1) {
        if (tid < o) red[tid] += red[tid + o];
        __syncthreads();
    }
    float mean = red[0] * (1.0f / D_);
    __syncthreads();

    float vs = 0.f;
    for (int d = tid; d < D_; d += 256) { float dv = x[d] - mean; vs += dv * dv; }
    red[tid] = vs; __syncthreads();
    for (int o = 128; o > 0; o >>= 1) {
        if (tid < o) red[tid] += red[tid + o];
        __syncthreads();
    }
    float rstd = rsqrtf(red[0] * (1.0f / D_) + EPS_);

    float* y = out + (size_t)row * D_;
    for (int d = tid; d < D_; d += 256)
        y[d] = (x[d] - mean) * rstd * scale[d] + bias[d];
}

// ---------------------------------------------------------------------------
// Tiled SGEMM: C[M,N] = A[M,K] @ B (+bias +residual, optional GELU)
//   TRANSB=false : B is [K,N] row-major   (all layer weights)
//   TRANSB=true  : B is [N,K] row-major   (lm head vs tok_emb)
// BM=BN=64, BK=16, 256 threads, 4x4 micro-tile, float4 smem reads.
// M and K are multiples of 64/16; only N needs guarding.
// ---------------------------------------------------------------------------
__device__ __forceinline__ float gelu_exact(float v) {
    return 0.5f * v * (1.f + erff(v * 0.70710678118654752f));
}

template <bool TRANSB, bool GELU>
__global__ void __launch_bounds__(256)
gemm_kernel(const float* __restrict__ A, const float* __restrict__ B,
            const float* __restrict__ bias, const float* __restrict__ res,
            float* __restrict__ C, int M, int N, int K) {
    const int BM = 64, BN = 64, BK = 16;
    __shared__ float As[BK][BM];
    __shared__ float Bs[BK][BN];

    int bm = blockIdx.y * BM;
    int bn = blockIdx.x * BN;
    int tid = threadIdx.x;
    int tx = tid & 15;          // 0..15 -> n micro-tile
    int ty = tid >> 4;          // 0..15 -> m micro-tile

    float acc[4][4] = {};

    for (int k0 = 0; k0 < K; k0 += BK) {
        // A tile: 64x16, consecutive tid -> consecutive k (coalesced 64B runs)
        #pragma unroll
        for (int i = 0; i < 4; i++) {
            int idx = tid + i * 256;
            int k = idx & 15, m = idx >> 4;
            As[k][m] = A[(size_t)(bm + m) * K + k0 + k];
        }
        // B tile: 16x64
        #pragma unroll
        for (int i = 0; i < 4; i++) {
            int idx = tid + i * 256;
            int k, n;
            if (TRANSB) { k = idx & 15; n = idx >> 4; }
            else        { n = idx & 63; k = idx >> 6; }
            int col = bn + n;
            float v = 0.f;
            if (col < N)
                v = TRANSB ? B[(size_t)col * K + k0 + k]
                           : B[(size_t)(k0 + k) * N + col];
            Bs[k][n] = v;
        }
        __syncthreads();

        #pragma unroll
        for (int k = 0; k < BK; k++) {
            float4 a4 = *reinterpret_cast<const float4*>(&As[k][ty * 4]);
            float4 b4 = *reinterpret_cast<const float4*>(&Bs[k][tx * 4]);
            float a[4] = {a4.x, a4.y, a4.z, a4.w};
            float b[4] = {b4.x, b4.y, b4.z, b4.w};
            #pragma unroll
            for (int i = 0; i < 4; i++)
                #pragma unroll
                for (int j = 0; j < 4; j++)
                    acc[i][j] = fmaf(a[i], b[j], acc[i][j]);
        }
        __syncthreads();
    }

    #pragma unroll
    for (int i = 0; i < 4; i++) {
        int row = bm + ty * 4 + i;
        #pragma unroll
        for (int j = 0; j < 4; j++) {
            int col = bn + tx * 4 + j;
            if (col < N) {
                float v = acc[i][j];
                if (bias) v += bias[col];
                if (res)  v += res[(size_t)row * N + col];
                if (GELU) v = gelu_exact(v);
                C[(size_t)row * N + col] = v;
            }
        }
    }
}

// ---------------------------------------------------------------------------
// Causal attention, one block per (b, h, q) row.
// scores in smem, softmax, stream V. scale = 1/sqrt(64) = 0.125
// ---------------------------------------------------------------------------
__global__ void __launch_bounds__(128) attn_kernel() {
    int blk = blockIdx.x;
    int qi = blk & (T_ - 1);
    int h  = (blk >> 10) & (H_ - 1);
    int b  = blk >> 14;
    int tid = threadIdx.x;

    __shared__ float qv[HD_];
    __shared__ float s[T_];
    __shared__ float red[128];

    const size_t base = (size_t)(b * T_) * (3 * D_);
    const float* qrow = g_qkv + base + (size_t)qi * (3 * D_) + h * HD_;
    if (tid < HD_) qv[tid] = qrow[tid];
    __syncthreads();

    const int nk = qi + 1;
    const float scale = 0.125f;

    for (int k = tid; k < nk; k += 128) {
        const float* krow = g_qkv + base + (size_t)k * (3 * D_) + D_ + h * HD_;
        float acc = 0.f;
        #pragma unroll
        for (int d = 0; d < HD_; d += 4) {
            float4 k4 = *reinterpret_cast<const float4*>(krow + d);
            acc = fmaf(qv[d], k4.x, acc);
            acc = fmaf(qv[d + 1], k4.y, acc);
            acc = fmaf(qv[d + 2], k4.z, acc);
            acc = fmaf(qv[d + 3], k4.w, acc);
        }
        s[k] = acc * scale;
    }
    __syncthreads();

    // max-reduce
    float m = -INFINITY;
    for (int k = tid; k < nk; k += 128) m = fmaxf(m, s[k]);
    red[tid] = m; __syncthreads();
    for (int o = 64; o > 0; o >>= 1) {
        if (tid < o) red[tid] = fmaxf(red[tid], red[tid + o]);
        __syncthreads();
    }
    m = red[0]; __syncthreads();

    // exp + sum-reduce
    float sum = 0.f;
    for (int k = tid; k < nk; k += 128) {
        float e = expf(s[k] - m);
        s[k] = e;
        sum += e;
    }
    red[tid] = sum; __syncthreads();
    for (int o = 64; o > 0; o >>= 1) {
        if (tid < o) red[tid] += red[tid + o];
        __syncthreads();
    }
    float inv = 1.f / red[0];
    __syncthreads();

    // output: thread d accumulates over k (coalesced V reads across threads)
    if (tid < HD_) {
        const float* vcol = g_qkv + base + 2 * D_ + h * HD_ + tid;
        float o = 0.f;
        for (int k = 0; k < nk; k++)
            o = fmaf(s[k], vcol[(size_t)k * (3 * D_)], o);
        g_o[(size_t)(b * T_ + qi) * D_ + h * HD_ + tid] = o * inv;
    }
}

// ---------------------------------------------------------------------------
// Host orchestration
// ---------------------------------------------------------------------------
static inline dim3 gemm_grid(int M, int N) {
    return dim3((N + 63) / 64, M / 64);
}

extern "C" void kernel_launch(void* const* d_in, const int* in_sizes, int n_in,
                              void* d_out, int out_size) {
    (void)in_sizes; (void)n_in; (void)out_size;
    const int*   idx    = (const int*)  d_in[0];
    const float* tok    = (const float*)d_in[1];
    const float* pos    = (const float*)d_in[2];
    const float* qkv_w  = (const float*)d_in[3];
    const float* qkv_b  = (const float*)d_in[4];
    const float* proj_w = (const float*)d_in[5];
    const float* proj_b = (const float*)d_in[6];
    const float* ff1_w  = (const float*)d_in[7];
    const float* ff1_b  = (const float*)d_in[8];
    const float* ff2_w  = (const float*)d_in[9];
    const float* ff2_b  = (const float*)d_in[10];
    const float* ln1_s  = (const float*)d_in[11];
    const float* ln1_b  = (const float*)d_in[12];
    const float* ln2_s  = (const float*)d_in[13];
    const float* ln2_b  = (const float*)d_in[14];
    const float* lnf_s  = (const float*)d_in[15];
    const float* lnf_b  = (const float*)d_in[16];
    float* out = (float*)d_out;

    float *px, *ph, *pqkv, *po, *pff;
    cudaGetSymbolAddress((void**)&px,   g_x);
    cudaGetSymbolAddress((void**)&ph,   g_h);
    cudaGetSymbolAddress((void**)&pqkv, g_qkv);
    cudaGetSymbolAddress((void**)&po,   g_o);
    cudaGetSymbolAddress((void**)&pff,  g_ff);

    embed_kernel<<<NT_, 256>>>(idx, tok, pos);

    for (int l = 0; l < L_; l++) {
        // ln1
        ln_kernel<<<NT_, 256>>>(px, ph, ln1_s + (size_t)l * D_, ln1_b + (size_t)l * D_);
        // qkv = h @ qkv_w + qkv_b   [4096,1024]@[1024,3072]
        gemm_kernel<false, false><<<gemm_grid(NT_, 3 * D_), 256>>>(
            ph, qkv_w + (size_t)l * D_ * 3 * D_, qkv_b + (size_t)l * 3 * D_,
            nullptr, pqkv, NT_, 3 * D_, D_);
        // attention
        attn_kernel<<<B_ * H_ * T_, 128>>>();
        // x = x + o @ proj_w + proj_b
        gemm_kernel<false, false><<<gemm_grid(NT_, D_), 256>>>(
            po, proj_w + (size_t)l * D_ * D_, proj_b + (size_t)l * D_,
            px, px, NT_, D_, D_);
        // ln2
        ln_kernel<<<NT_, 256>>>(px, ph, ln2_s + (size_t)l * D_, ln2_b + (size_t)l * D_);
        // ff = gelu(h @ ff1_w + ff1_b)   [4096,1024]@[1024,4096]
        gemm_kernel<false, true><<<gemm_grid(NT_, 4 * D_), 256>>>(
            ph, ff1_w + (size_t)l * D_ * 4 * D_, ff1_b + (size_t)l * 4 * D_,
            nullptr, pff, NT_, 4 * D_, D_);
        // x = x + ff @ ff2_w + ff2_b   [4096,4096]@[4096,1024]
        gemm_kernel<false, false><<<gemm_grid(NT_, D_), 256>>>(
            pff, ff2_w + (size_t)l * 4 * D_ * D_, ff2_b + (size_t)l * D_,
            px, px, NT_, D_, 4 * D_);
    }

    // final LN
    ln_kernel<<<NT_, 256>>>(px, ph, lnf_s, lnf_b);
    // logits = h @ tok_emb^T   [4096,1024]@[1024,50257] (B transposed)
    gemm_kernel<true, false><<<gemm_grid(NT_, V_), 256>>>(
        ph, tok, nullptr, nullptr, out, NT_, V_, D_);
}

// round 3
// speedup vs baseline: 2.7896x; 2.7896x over previous
#include <cuda_runtime.h>
#include <cstdint>
#include <math.h>

// ---- Problem constants ----
#define B_  4
#define T_  1024
#define D_  1024
#define H_  16
#define L_  8
#define V_  50257
#define HD_ 64
#define NT_ (B_ * T_)          // 4096 token rows
#define EPS_ 1e-5f

// ---- Scratch (device globals; no allocation allowed) ----
__device__ float g_x  [NT_ * D_];        // residual stream
__device__ float g_h  [NT_ * D_];        // layernorm output
__device__ float g_qkv[NT_ * 3 * D_];    // qkv
__device__ float g_o  [NT_ * D_];        // attention output
__device__ float g_ff [NT_ * 4 * D_];    // ff1 output

// Transposed weights ([N,K] row-major, i.e. K-contiguous for B-fragments)
__device__ float g_qkvT[L_ * 3 * D_ * D_];
__device__ float g_projT[L_ * D_ * D_];
__device__ float g_ff1T [L_ * 4 * D_ * D_];
__device__ float g_ff2T [L_ * D_ * 4 * D_];

// ===========================================================================
// tf32 helpers
// ===========================================================================
__device__ __forceinline__ float to_tf32(float x) {
    float y;
    asm("cvt.rna.tf32.f32 %0, %1;" : "=f"(y) : "f"(x));
    return y;
}
__device__ __forceinline__ void split4(float4 v, float4& hi, float4& lo) {
    hi.x = to_tf32(v.x); lo.x = to_tf32(v.x - hi.x);
    hi.y = to_tf32(v.y); lo.y = to_tf32(v.y - hi.y);
    hi.z = to_tf32(v.z); lo.z = to_tf32(v.z - hi.z);
    hi.w = to_tf32(v.w); lo.w = to_tf32(v.w - hi.w);
}

__device__ __forceinline__ void mma_tf32(float c[4], const uint32_t a[4],
                                         const uint32_t b[2]) {
    asm volatile(
        "mma.sync.aligned.m16n8k8.row.col.f32.tf32.tf32.f32 "
        "{%0,%1,%2,%3}, {%4,%5,%6,%7}, {%8,%9}, {%0,%1,%2,%3};"
        : "+f"(c[0]), "+f"(c[1]), "+f"(c[2]), "+f"(c[3])
        : "r"(a[0]), "r"(a[1]), "r"(a[2]), "r"(a[3]), "r"(b[0]), "r"(b[1]));
}

__device__ __forceinline__ float gelu_exact(float v) {
    return 0.5f * v * (1.f + erff(v * 0.70710678118654752f));
}

// ===========================================================================
// 3xTF32 mma.sync GEMM: C[M,N] = A[M,K] @ Bt[N,K]^T  (+bias +res, opt GELU)
// BM=BN=128, BK=16, 256 threads (8 warps), warp tile 32x64 (2x8 frags),
// double-buffered smem, pad-20 rows (conflict-free fragment LDS).
// M % 128 == 0, K % 16 == 0; N guarded.
// ===========================================================================
#define GBM 128
#define GBN 128
#define GBK 16
#define PAD_ 20
#define TILEF (128 * PAD_)       // floats per (operand, hi-or-lo) tile = 2560
#define STAGEF (4 * TILEF)       // Ah, Al, Bh, Bl
#define GEMM_SMEM (2 * STAGEF * 4)   // bytes = 81920

template <bool GELU>
__global__ void __launch_bounds__(256)
mma_gemm(const float* __restrict__ A, const float* __restrict__ Bt,
         const float* __restrict__ bias, const float* __restrict__ res,
         float* __restrict__ C, int N, int K) {
    extern __shared__ float smem[];

    const int tid  = threadIdx.x;
    const int wid  = tid >> 5;
    const int lane = tid & 31;
    const int g    = lane >> 2;       // 0..7
    const int t    = lane & 3;        // 0..3
    const int warp_m = (wid & 3) * 32;
    const int warp_n = (wid >> 2) * 64;
    const int bm = blockIdx.x * GBM;
    const int bn = blockIdx.y * GBN;

    float acc[2][8][4];
    #pragma unroll
    for (int mf = 0; mf < 2; mf++)
        #pragma unroll
        for (int nf = 0; nf < 8; nf++)
            #pragma unroll
            for (int i = 0; i < 4; i++) acc[mf][nf][i] = 0.f;

    const int NC = K >> 4;
    float4 ra[2], rb[2];

    // row/quad this thread loads (same for every chunk)
    int lrow[2], lq[2];
    #pragma unroll
    for (int i = 0; i < 2; i++) {
        int j = tid + (i << 8);
        lrow[i] = j >> 2;
        lq[i]   = j & 3;
    }

    // ---- prefetch chunk 0 ----
    #pragma unroll
    for (int i = 0; i < 2; i++) {
        ra[i] = *reinterpret_cast<const float4*>(
            A + (size_t)(bm + lrow[i]) * K + (lq[i] << 2));
        int n = bn + lrow[i];
        rb[i] = (n < N) ? *reinterpret_cast<const float4*>(
                              Bt + (size_t)n * K + (lq[i] << 2))
                        : make_float4(0.f, 0.f, 0.f, 0.f);
    }
    // ---- STS stage 0 ----
    {
        float* st = smem;       // stage 0
        #pragma unroll
        for (int i = 0; i < 2; i++) {
            float4 h, l;
            int off = lrow[i] * PAD_ + (lq[i] << 2);
            split4(ra[i], h, l);
            *reinterpret_cast<float4*>(st + off)            = h;
            *reinterpret_cast<float4*>(st + TILEF + off)    = l;
            split4(rb[i], h, l);
            *reinterpret_cast<float4*>(st + 2 * TILEF + off) = h;
            *reinterpret_cast<float4*>(st + 3 * TILEF + off) = l;
        }
    }
    __syncthreads();

    for (int c = 0; c < NC; c++) {
        const int cur = c & 1;
        const bool more = (c + 1 < NC);
        if (more) {
            const int k0 = (c + 1) << 4;
            #pragma unroll
            for (int i = 0; i < 2; i++) {
                ra[i] = *reinterpret_cast<const float4*>(
                    A + (size_t)(bm + lrow[i]) * K + k0 + (lq[i] << 2));
                int n = bn + lrow[i];
                rb[i] = (n < N) ? *reinterpret_cast<const float4*>(
                                      Bt + (size_t)n * K + k0 + (lq[i] << 2))
                                : make_float4(0.f, 0.f, 0.f, 0.f);
            }
        }

        const float* Ah = smem + cur * STAGEF;
        const float* Bh = Ah + 2 * TILEF;

        #pragma unroll
        for (int ko = 0; ko < 2; ko++) {
            const int kb = ko * 8;
            uint32_t ah[2][4], al[2][4];
            #pragma unroll
            for (int mf = 0; mf < 2; mf++) {
                const float* p = Ah + (warp_m + mf * 16 + g) * PAD_ + kb + t;
                ah[mf][0] = __float_as_uint(p[0]);
                ah[mf][1] = __float_as_uint(p[8 * PAD_]);
                ah[mf][2] = __float_as_uint(p[4]);
                ah[mf][3] = __float_as_uint(p[8 * PAD_ + 4]);
                const float* q2 = p + TILEF;
                al[mf][0] = __float_as_uint(q2[0]);
                al[mf][1] = __float_as_uint(q2[8 * PAD_]);
                al[mf][2] = __float_as_uint(q2[4]);
                al[mf][3] = __float_as_uint(q2[8 * PAD_ + 4]);
            }
            uint32_t bh[8][2], bl[8][2];
            #pragma unroll
            for (int nf = 0; nf < 8; nf++) {
                const float* p = Bh + (warp_n + nf * 8 + g) * PAD_ + kb + t;
                bh[nf][0] = __float_as_uint(p[0]);
                bh[nf][1] = __float_as_uint(p[4]);
                const float* q2 = p + TILEF;
                bl[nf][0] = __float_as_uint(q2[0]);
                bl[nf][1] = __float_as_uint(q2[4]);
            }
            #pragma unroll
            for (int mf = 0; mf < 2; mf++)
                #pragma unroll
                for (int nf = 0; nf < 8; nf++) {
                    mma_tf32(acc[mf][nf], ah[mf], bh[nf]);
                    mma_tf32(acc[mf][nf], ah[mf], bl[nf]);
                    mma_tf32(acc[mf][nf], al[mf], bh[nf]);
                }
        }

        if (more) {
            float* st = smem + ((c + 1) & 1) * STAGEF;
            #pragma unroll
            for (int i = 0; i < 2; i++) {
                float4 h, l;
                int off = lrow[i] * PAD_ + (lq[i] << 2);
                split4(ra[i], h, l);
                *reinterpret_cast<float4*>(st + off)             = h;
                *reinterpret_cast<float4*>(st + TILEF + off)     = l;
                split4(rb[i], h, l);
                *reinterpret_cast<float4*>(st + 2 * TILEF + off) = h;
                *reinterpret_cast<float4*>(st + 3 * TILEF + off) = l;
            }
            __syncthreads();
        }
    }

    // ---- epilogue ----
    #pragma unroll
    for (int mf = 0; mf < 2; mf++) {
        #pragma unroll
        for (int nf = 0; nf < 8; nf++) {
            int r0 = bm + warp_m + mf * 16 + g;
            int c0 = bn + warp_n + nf * 8 + 2 * t;
            #pragma unroll
            for (int i = 0; i < 4; i++) {
                int row = r0 + ((i >> 1) << 3);   // +8 for c2/c3
                int col = c0 + (i & 1);
                if (col < N) {
                    float v = acc[mf][nf][i];
                    if (bias) v += bias[col];
                    if (res)  v += res[(size_t)row * N + col];
                    if (GELU) v = gelu_exact(v);
                    C[(size_t)row * N + col] = v;
                }
            }
        }
    }
}

// ===========================================================================
// Weight transpose: out[n*K+k] = in[k*N+n]
// ===========================================================================
__global__ void __launch_bounds__(256)
transpose_kernel(const float* __restrict__ in, float* __restrict__ out,
                 int K, int N) {
    __shared__ float tbuf[32][33];
    int n0 = blockIdx.x * 32, k0 = blockIdx.y * 32;
    int tx = threadIdx.x, ty = threadIdx.y;   // 32 x 8
    #pragma unroll
    for (int i = 0; i < 4; i++)
        tbuf[ty + 8 * i][tx] = in[(size_t)(k0 + ty + 8 * i) * N + n0 + tx];
    __syncthreads();
    #pragma unroll
    for (int i = 0; i < 4; i++)
        out[(size_t)(n0 + ty + 8 * i) * K + k0 + tx] = tbuf[tx][ty + 8 * i];
}

// ===========================================================================
// Embedding
// ===========================================================================
__global__ void embed_kernel(const int* __restrict__ idx,
                             const float* __restrict__ tok,
                             const float* __restrict__ pos) {
    int row = blockIdx.x;
    int t   = row & (T_ - 1);
    int v   = idx[row];
    const float* tr = tok + (size_t)v * D_;
    const float* pr = pos + (size_t)t * D_;
    float* xr = g_x + (size_t)row * D_;
    for (int d = threadIdx.x; d < D_; d += blockDim.x)
        xr[d] = tr[d] + pr[d];
}

// ===========================================================================
// LayerNorm
// ===========================================================================
__global__ void ln_kernel(const float* __restrict__ in, float* __restrict__ out,
                          const float* __restrict__ scale,
                          const float* __restrict__ bias) {
    __shared__ float red[256];
    int row = blockIdx.x;
    int tid = threadIdx.x;
    const float* x = in + (size_t)row * D_;

    float s = 0.f;
    for (int d = tid; d < D_; d += 256) s += x[d];
    red[tid] = s; __syncthreads();
    for (int o = 128; o > 0; o >>= 1) {
        if (tid < o) red[tid] += red[tid + o];
        __syncthreads();
    }
    float mean = red[0] * (1.0f / D_);
    __syncthreads();

    float vs = 0.f;
    for (int d = tid; d < D_; d += 256) { float dv = x[d] - mean; vs += dv * dv; }
    red[tid] = vs; __syncthreads();
    for (int o = 128; o > 0; o >>= 1) {
        if (tid < o) red[tid] += red[tid + o];
        __syncthreads();
    }
    float rstd = rsqrtf(red[0] * (1.0f / D_) + EPS_);

    float* y = out + (size_t)row * D_;
    for (int d = tid; d < D_; d += 256)
        y[d] = (x[d] - mean) * rstd * scale[d] + bias[d];
}

// ===========================================================================
// Causal attention, one block per (b, h, q) row (fp32)
// ===========================================================================
__global__ void __launch_bounds__(128) attn_kernel() {
    int blk = blockIdx.x;
    int qi = blk & (T_ - 1);
    int h  = (blk >> 10) & (H_ - 1);
    int b  = blk >> 14;
    int tid = threadIdx.x;

    __shared__ float qv[HD_];
    __shared__ float s[T_];
    __shared__ float red[128];

    const size_t base = (size_t)(b * T_) * (3 * D_);
    const float* qrow = g_qkv + base + (size_t)qi * (3 * D_) + h * HD_;
    if (tid < HD_) qv[tid] = qrow[tid];
    __syncthreads();

    const int nk = qi + 1;
    const float scale = 0.125f;

    for (int k = tid; k < nk; k += 128) {
        const float* krow = g_qkv + base + (size_t)k * (3 * D_) + D_ + h * HD_;
        float acc = 0.f;
        #pragma unroll
        for (int d = 0; d < HD_; d += 4) {
            float4 k4 = *reinterpret_cast<const float4*>(krow + d);
            acc = fmaf(qv[d], k4.x, acc);
            acc = fmaf(qv[d + 1], k4.y, acc);
            acc = fmaf(qv[d + 2], k4.z, acc);
            acc = fmaf(qv[d + 3], k4.w, acc);
        }
        s[k] = acc * scale;
    }
    __syncthreads();

    float m = -INFINITY;
    for (int k = tid; k < nk; k += 128) m = fmaxf(m, s[k]);
    red[tid] = m; __syncthreads();
    for (int o = 64; o > 0; o >>= 1) {
        if (tid < o) red[tid] = fmaxf(red[tid], red[tid + o]);
        __syncthreads();
    }
    m = red[0]; __syncthreads();

    float sum = 0.f;
    for (int k = tid; k < nk; k += 128) {
        float e = expf(s[k] - m);
        s[k] = e;
        sum += e;
    }
    red[tid] = sum; __syncthreads();
    for (int o = 64; o > 0; o >>= 1) {
        if (tid < o) red[tid] += red[tid + o];
        __syncthreads();
    }
    float inv = 1.f / red[0];
    __syncthreads();

    if (tid < HD_) {
        const float* vcol = g_qkv + base + 2 * D_ + h * HD_ + tid;
        float o = 0.f;
        for (int k = 0; k < nk; k++)
            o = fmaf(s[k], vcol[(size_t)k * (3 * D_)], o);
        g_o[(size_t)(b * T_ + qi) * D_ + h * HD_ + tid] = o * inv;
    }
}

// ===========================================================================
// Host orchestration
// ===========================================================================
static inline dim3 tcg_grid(int N) {
    return dim3(NT_ / GBM, (N + GBN - 1) / GBN);
}

extern "C" void kernel_launch(void* const* d_in, const int* in_sizes, int n_in,
                              void* d_out, int out_size) {
    (void)in_sizes; (void)n_in; (void)out_size;
    const int*   idx    = (const int*)  d_in[0];
    const float* tok    = (const float*)d_in[1];
    const float* pos    = (const float*)d_in[2];
    const float* qkv_w  = (const float*)d_in[3];
    const float* qkv_b  = (const float*)d_in[4];
    const float* proj_w = (const float*)d_in[5];
    const float* proj_b = (const float*)d_in[6];
    const float* ff1_w  = (const float*)d_in[7];
    const float* ff1_b  = (const float*)d_in[8];
    const float* ff2_w  = (const float*)d_in[9];
    const float* ff2_b  = (const float*)d_in[10];
    const float* ln1_s  = (const float*)d_in[11];
    const float* ln1_b  = (const float*)d_in[12];
    const float* ln2_s  = (const float*)d_in[13];
    const float* ln2_b  = (const float*)d_in[14];
    const float* lnf_s  = (const float*)d_in[15];
    const float* lnf_b  = (const float*)d_in[16];
    float* out = (float*)d_out;

    float *px, *ph, *pqkv, *po, *pff, *pqkvT, *pprojT, *pff1T, *pff2T;
    cudaGetSymbolAddress((void**)&px,    g_x);
    cudaGetSymbolAddress((void**)&ph,    g_h);
    cudaGetSymbolAddress((void**)&pqkv,  g_qkv);
    cudaGetSymbolAddress((void**)&po,    g_o);
    cudaGetSymbolAddress((void**)&pff,   g_ff);
    cudaGetSymbolAddress((void**)&pqkvT, g_qkvT);
    cudaGetSymbolAddress((void**)&pprojT, g_projT);
    cudaGetSymbolAddress((void**)&pff1T, g_ff1T);
    cudaGetSymbolAddress((void**)&pff2T, g_ff2T);

    cudaFuncSetAttribute(mma_gemm<false>,
                         cudaFuncAttributeMaxDynamicSharedMemorySize, GEMM_SMEM);
    cudaFuncSetAttribute(mma_gemm<true>,
                         cudaFuncAttributeMaxDynamicSharedMemorySize, GEMM_SMEM);

    // Pre-transpose all layer weights: [K,N] -> [N,K]
    dim3 tb(32, 8);
    for (int l = 0; l < L_; l++) {
        transpose_kernel<<<dim3(3 * D_ / 32, D_ / 32), tb>>>(
            qkv_w + (size_t)l * D_ * 3 * D_, pqkvT + (size_t)l * 3 * D_ * D_, D_, 3 * D_);
        transpose_kernel<<<dim3(D_ / 32, D_ / 32), tb>>>(
            proj_w + (size_t)l * D_ * D_, pprojT + (size_t)l * D_ * D_, D_, D_);
        transpose_kernel<<<dim3(4 * D_ / 32, D_ / 32), tb>>>(
            ff1_w + (size_t)l * D_ * 4 * D_, pff1T + (size_t)l * 4 * D_ * D_, D_, 4 * D_);
        transpose_kernel<<<dim3(D_ / 32, 4 * D_ / 32), tb>>>(
            ff2_w + (size_t)l * 4 * D_ * D_, pff2T + (size_t)l * D_ * 4 * D_, 4 * D_, D_);
    }

    embed_kernel<<<NT_, 256>>>(idx, tok, pos);

    for (int l = 0; l < L_; l++) {
        ln_kernel<<<NT_, 256>>>(px, ph, ln1_s + (size_t)l * D_, ln1_b + (size_t)l * D_);
        // qkv = h @ qkv_w + qkv_b
        mma_gemm<false><<<tcg_grid(3 * D_), 256, GEMM_SMEM>>>(
            ph, pqkvT + (size_t)l * 3 * D_ * D_, qkv_b + (size_t)l * 3 * D_,
            nullptr, pqkv, 3 * D_, D_);
        attn_kernel<<<B_ * H_ * T_, 128>>>();
        // x = x + o @ proj_w + proj_b
        mma_gemm<false><<<tcg_grid(D_), 256, GEMM_SMEM>>>(
            po, pprojT + (size_t)l * D_ * D_, proj_b + (size_t)l * D_,
            px, px, D_, D_);
        ln_kernel<<<NT_, 256>>>(px, ph, ln2_s + (size_t)l * D_, ln2_b + (size_t)l * D_);
        // ff = gelu(h @ ff1_w + ff1_b)
        mma_gemm<true><<<tcg_grid(4 * D_), 256, GEMM_SMEM>>>(
            ph, pff1T + (size_t)l * 4 * D_ * D_, ff1_b + (size_t)l * 4 * D_,
            nullptr, pff, 4 * D_, D_);
        // x = x + ff @ ff2_w + ff2_b
        mma_gemm<false><<<tcg_grid(D_), 256, GEMM_SMEM>>>(
            pff, pff2T + (size_t)l * D_ * 4 * D_, ff2_b + (size_t)l * D_,
            px, px, D_, 4 * D_);
    }

    ln_kernel<<<NT_, 256>>>(px, ph, lnf_s, lnf_b);
    // logits = h @ tok_emb^T : tok_emb is [V,D] = [N,K] K-contiguous already
    mma_gemm<false><<<tcg_grid(V_), 256, GEMM_SMEM>>>(
        ph, tok, nullptr, nullptr, out, V_, D_);
}

// round 4
// speedup vs baseline: 3.7275x; 1.3362x over previous
#include <cuda_runtime.h>
#include <cuda_fp16.h>
#include <cstdint>
#include <math.h>

// ---- Problem constants ----
#define B_  4
#define T_  1024
#define D_  1024
#define H_  16
#define L_  8
#define V_  50257
#define HD_ 64
#define NT_ (B_ * T_)          // 4096 token rows
#define EPS_ 1e-5f

// ---- Scratch (device globals; no allocation allowed) ----
__device__ float  g_x  [NT_ * D_];          // residual stream (fp32)
__device__ float  g_qkv[NT_ * 3 * D_];      // qkv (fp32)
__device__ __half g_h_h [NT_ * D_];         // layernorm out hi/lo
__device__ __half g_h_l [NT_ * D_];
__device__ __half g_o_h [NT_ * D_];         // attention out hi/lo
__device__ __half g_o_l [NT_ * D_];
__device__ __half g_ff_h[NT_ * 4 * D_];     // ff1/gelu out hi/lo
__device__ __half g_ff_l[NT_ * 4 * D_];

// Pre-transposed, pre-split weights ([N,K] K-contiguous, fp16 hi/lo)
__device__ __half g_qkvT_h[L_ * 3 * D_ * D_];
__device__ __half g_qkvT_l[L_ * 3 * D_ * D_];
__device__ __half g_projT_h[L_ * D_ * D_];
__device__ __half g_projT_l[L_ * D_ * D_];
__device__ __half g_ff1T_h[L_ * 4 * D_ * D_];
__device__ __half g_ff1T_l[L_ * 4 * D_ * D_];
__device__ __half g_ff2T_h[L_ * D_ * 4 * D_];
__device__ __half g_ff2T_l[L_ * D_ * 4 * D_];
__device__ __half g_tok_h[(size_t)V_ * D_];
__device__ __half g_tok_l[(size_t)V_ * D_];

// ===========================================================================
// helpers
// ===========================================================================
__device__ __forceinline__ void split_h(float x, __half& h, __half& l) {
    h = __float2half_rn(x);
    l = __float2half_rn(x - __half2float(h));
}
__device__ __forceinline__ uint32_t smem_u32(const void* p) {
    uint32_t a;
    asm("{ .reg .u64 t; cvta.to.shared.u64 t, %1; cvt.u32.u64 %0, t; }"
        : "=r"(a) : "l"(p));
    return a;
}
__device__ __forceinline__ void mma_f16(float c[4], const uint32_t a[4],
                                        const uint32_t b[2]) {
    asm volatile(
        "mma.sync.aligned.m16n8k16.row.col.f32.f16.f16.f32 "
        "{%0,%1,%2,%3}, {%4,%5,%6,%7}, {%8,%9}, {%0,%1,%2,%3};"
        : "+f"(c[0]), "+f"(c[1]), "+f"(c[2]), "+f"(c[3])
        : "r"(a[0]), "r"(a[1]), "r"(a[2]), "r"(a[3]), "r"(b[0]), "r"(b[1]));
}
__device__ __forceinline__ void ldsm4(uint32_t r[4], uint32_t addr) {
    asm volatile("ldmatrix.sync.aligned.m8n8.x4.shared.b16 {%0,%1,%2,%3}, [%4];"
                 : "=r"(r[0]), "=r"(r[1]), "=r"(r[2]), "=r"(r[3]) : "r"(addr));
}
__device__ __forceinline__ float gelu_exact(float v) {
    return 0.5f * v * (1.f + erff(v * 0.70710678118654752f));
}

// ===========================================================================
// fp16 3-product mma GEMM: C[M,N] = A[M,K] @ Bt[N,K]^T (+bias +res / gelu)
// A,B given as pre-split fp16 hi/lo arrays.  BM=BN=128, BK=16, 256 threads,
// warp tile 32x64, ldmatrix fragments, 48B padded rows (conflict-free).
// MODE 0: fp32 C (+bias,+res opt).  MODE 1: gelu, split to Ch/Cl halves.
// ===========================================================================
#define GBM 128
#define GBN 128
#define GBK 16
#define ROWB 48                  // bytes per smem tile row (16 fp16 + 8 pad)
#define TILEB (128 * ROWB)       // 6144 B
#define STAGEB (4 * TILEB)       // Ah, Al, Bh, Bl = 24576 B
#define GEMM_SMEM (2 * STAGEB)   // 49152 B

template <int MODE>
__global__ void __launch_bounds__(256)
mma_gemm(const __half* __restrict__ Ah_g, const __half* __restrict__ Al_g,
         const __half* __restrict__ Bh_g, const __half* __restrict__ Bl_g,
         const float* __restrict__ bias, const float* __restrict__ res,
         float* __restrict__ C, __half* __restrict__ Ch, __half* __restrict__ Cl,
         int N, int K) {
    extern __shared__ char smem[];
    const uint32_t sb = smem_u32(smem);

    const int tid  = threadIdx.x;
    const int wid  = tid >> 5;
    const int lane = tid & 31;
    const int g    = lane >> 2;
    const int t    = lane & 3;
    const int warp_m = (wid & 3) * 32;
    const int warp_n = (wid >> 2) * 64;
    const int bm = blockIdx.x * GBM;
    const int bn = blockIdx.y * GBN;

    float acc[2][8][4];
    #pragma unroll
    for (int mf = 0; mf < 2; mf++)
        #pragma unroll
        for (int nf = 0; nf < 8; nf++)
            #pragma unroll
            for (int i = 0; i < 4; i++) acc[mf][nf][i] = 0.f;

    // loader indices: thread covers (row, 4 k-values)
    int lrow[2], lq[2];
    #pragma unroll
    for (int i = 0; i < 2; i++) {
        int j = tid + (i << 8);
        lrow[i] = j >> 2;       // 0..127
        lq[i]   = j & 3;        // 0..3 -> k offset 4q
    }

    const int NC = K >> 4;
    uint2 rah[2], ral[2], rbh[2], rbl[2];

    // prefetch chunk 0
    #pragma unroll
    for (int i = 0; i < 2; i++) {
        size_t aoff = (size_t)(bm + lrow[i]) * K + (lq[i] << 2);
        rah[i] = *reinterpret_cast<const uint2*>(Ah_g + aoff);
        ral[i] = *reinterpret_cast<const uint2*>(Al_g + aoff);
        int n = bn + lrow[i];
        if (n < N) {
            size_t boff = (size_t)n * K + (lq[i] << 2);
            rbh[i] = *reinterpret_cast<const uint2*>(Bh_g + boff);
            rbl[i] = *reinterpret_cast<const uint2*>(Bl_g + boff);
        } else {
            rbh[i] = make_uint2(0u, 0u);
            rbl[i] = make_uint2(0u, 0u);
        }
    }
    // STS stage 0
    {
        char* st = smem;
        #pragma unroll
        for (int i = 0; i < 2; i++) {
            int off = lrow[i] * ROWB + (lq[i] << 3);
            *reinterpret_cast<uint2*>(st + off)             = rah[i];
            *reinterpret_cast<uint2*>(st + TILEB + off)     = ral[i];
            *reinterpret_cast<uint2*>(st + 2 * TILEB + off) = rbh[i];
            *reinterpret_cast<uint2*>(st + 3 * TILEB + off) = rbl[i];
        }
    }
    __syncthreads();

    // per-warp ldmatrix address offsets (within a tile)
    const uint32_t a_off = (uint32_t)(warp_m + (lane & 15)) * ROWB
                         + ((lane >> 4) << 4);
    const uint32_t b_off = (uint32_t)(warp_n + (lane & 7) + ((lane >> 4) << 3)) * ROWB
                         + (((lane >> 3) & 1) << 4);

    for (int c = 0; c < NC; c++) {
        const int cur = c & 1;
        const bool more = (c + 1 < NC);
        if (more) {
            const int k0 = (c + 1) << 4;
            #pragma unroll
            for (int i = 0; i < 2; i++) {
                size_t aoff = (size_t)(bm + lrow[i]) * K + k0 + (lq[i] << 2);
                rah[i] = *reinterpret_cast<const uint2*>(Ah_g + aoff);
                ral[i] = *reinterpret_cast<const uint2*>(Al_g + aoff);
                int n = bn + lrow[i];
                if (n < N) {
                    size_t boff = (size_t)n * K + k0 + (lq[i] << 2);
                    rbh[i] = *reinterpret_cast<const uint2*>(Bh_g + boff);
                    rbl[i] = *reinterpret_cast<const uint2*>(Bl_g + boff);
                } else {
                    rbh[i] = make_uint2(0u, 0u);
                    rbl[i] = make_uint2(0u, 0u);
                }
            }
        }

        const uint32_t base = sb + cur * STAGEB;
        uint32_t ah[2][4], al[2][4];
        ldsm4(ah[0], base + a_off);
        ldsm4(ah[1], base + a_off + 16 * ROWB);
        ldsm4(al[0], base + TILEB + a_off);
        ldsm4(al[1], base + TILEB + a_off + 16 * ROWB);

        uint32_t bh[8][2], bl[8][2];
        #pragma unroll
        for (int p = 0; p < 4; p++) {
            uint32_t r4[4];
            ldsm4(r4, base + 2 * TILEB + b_off + p * 16 * ROWB);
            bh[2 * p][0] = r4[0]; bh[2 * p][1] = r4[1];
            bh[2 * p + 1][0] = r4[2]; bh[2 * p + 1][1] = r4[3];
            ldsm4(r4, base + 3 * TILEB + b_off + p * 16 * ROWB);
            bl[2 * p][0] = r4[0]; bl[2 * p][1] = r4[1];
            bl[2 * p + 1][0] = r4[2]; bl[2 * p + 1][1] = r4[3];
        }

        #pragma unroll
        for (int mf = 0; mf < 2; mf++)
            #pragma unroll
            for (int nf = 0; nf < 8; nf++) {
                mma_f16(acc[mf][nf], ah[mf], bh[nf]);
                mma_f16(acc[mf][nf], ah[mf], bl[nf]);
                mma_f16(acc[mf][nf], al[mf], bh[nf]);
            }

        if (more) {
            char* st = smem + ((c + 1) & 1) * STAGEB;
            #pragma unroll
            for (int i = 0; i < 2; i++) {
                int off = lrow[i] * ROWB + (lq[i] << 3);
                *reinterpret_cast<uint2*>(st + off)             = rah[i];
                *reinterpret_cast<uint2*>(st + TILEB + off)     = ral[i];
                *reinterpret_cast<uint2*>(st + 2 * TILEB + off) = rbh[i];
                *reinterpret_cast<uint2*>(st + 3 * TILEB + off) = rbl[i];
            }
            __syncthreads();
        }
    }

    // epilogue
    #pragma unroll
    for (int mf = 0; mf < 2; mf++) {
        #pragma unroll
        for (int nf = 0; nf < 8; nf++) {
            int r0 = bm + warp_m + mf * 16 + g;
            int c0 = bn + warp_n + nf * 8 + 2 * t;
            #pragma unroll
            for (int i = 0; i < 4; i++) {
                int row = r0 + ((i >> 1) << 3);
                int col = c0 + (i & 1);
                if (col < N) {
                    float v = acc[mf][nf][i];
                    if (bias) v += bias[col];
                    if (MODE == 0) {
                        if (res) v += res[(size_t)row * N + col];
                        C[(size_t)row * N + col] = v;
                    } else {
                        v = gelu_exact(v);
                        __half h, l; split_h(v, h, l);
                        Ch[(size_t)row * N + col] = h;
                        Cl[(size_t)row * N + col] = l;
                    }
                }
            }
        }
    }
}

// ===========================================================================
// Weight transpose + fp16 split: out[n*K+k] = split(in[k*N+n])
// ===========================================================================
__global__ void __launch_bounds__(256)
transpose_split(const float* __restrict__ in, __half* __restrict__ oh,
                __half* __restrict__ ol, int K, int N) {
    __shared__ float tbuf[32][33];
    int n0 = blockIdx.x * 32, k0 = blockIdx.y * 32;
    int tx = threadIdx.x, ty = threadIdx.y;   // 32 x 8
    #pragma unroll
    for (int i = 0; i < 4; i++)
        tbuf[ty + 8 * i][tx] = in[(size_t)(k0 + ty + 8 * i) * N + n0 + tx];
    __syncthreads();
    #pragma unroll
    for (int i = 0; i < 4; i++) {
        float v = tbuf[tx][ty + 8 * i];
        __half h, l; split_h(v, h, l);
        size_t o = (size_t)(n0 + ty + 8 * i) * K + k0 + tx;
        oh[o] = h; ol[o] = l;
    }
}

// tok_emb split (already [V,D] K-contiguous): elementwise, float4 per thread
__global__ void __launch_bounds__(256)
tok_split(const float* __restrict__ tok) {
    size_t i = ((size_t)blockIdx.x * 256 + threadIdx.x) * 4;
    float4 v = *reinterpret_cast<const float4*>(tok + i);
    __half h, l;
    split_h(v.x, h, l); g_tok_h[i]     = h; g_tok_l[i]     = l;
    split_h(v.y, h, l); g_tok_h[i + 1] = h; g_tok_l[i + 1] = l;
    split_h(v.z, h, l); g_tok_h[i + 2] = h; g_tok_l[i + 2] = l;
    split_h(v.w, h, l); g_tok_h[i + 3] = h; g_tok_l[i + 3] = l;
}

// ===========================================================================
// Embedding (fp32 residual stream)
// ===========================================================================
__global__ void embed_kernel(const int* __restrict__ idx,
                             const float* __restrict__ tok,
                             const float* __restrict__ pos) {
    int row = blockIdx.x;
    int t   = row & (T_ - 1);
    int v   = idx[row];
    const float* tr = tok + (size_t)v * D_;
    const float* pr = pos + (size_t)t * D_;
    float* xr = g_x + (size_t)row * D_;
    for (int d = threadIdx.x; d < D_; d += blockDim.x)
        xr[d] = tr[d] + pr[d];
}

// ===========================================================================
// LayerNorm -> fp16 hi/lo
// ===========================================================================
__global__ void ln_split_kernel(const float* __restrict__ in,
                                __half* __restrict__ oh, __half* __restrict__ ol,
                                const float* __restrict__ scale,
                                const float* __restrict__ bias) {
    __shared__ float red[256];
    int row = blockIdx.x;
    int tid = threadIdx.x;
    const float* x = in + (size_t)row * D_;

    float s = 0.f;
    for (int d = tid; d < D_; d += 256) s += x[d];
    red[tid] = s; __syncthreads();
    for (int o = 128; o > 0; o >>= 1) {
        if (tid < o) red[tid] += red[tid + o];
        __syncthreads();
    }
    float mean = red[0] * (1.0f / D_);
    __syncthreads();

    float vs = 0.f;
    for (int d = tid; d < D_; d += 256) { float dv = x[d] - mean; vs += dv * dv; }
    red[tid] = vs; __syncthreads();
    for (int o = 128; o > 0; o >>= 1) {
        if (tid < o) red[tid] += red[tid + o];
        __syncthreads();
    }
    float rstd = rsqrtf(red[0] * (1.0f / D_) + EPS_);

    for (int d = tid; d < D_; d += 256) {
        float y = (x[d] - mean) * rstd * scale[d] + bias[d];
        __half h, l; split_h(y, h, l);
        oh[(size_t)row * D_ + d] = h;
        ol[(size_t)row * D_ + d] = l;
    }
}

// ===========================================================================
// Causal attention (fp32), writes fp16 hi/lo output
// ===========================================================================
__global__ void __launch_bounds__(128) attn_kernel() {
    int blk = blockIdx.x;
    int qi = blk & (T_ - 1);
    int h  = (blk >> 10) & (H_ - 1);
    int b  = blk >> 14;
    int tid = threadIdx.x;

    __shared__ float qv[HD_];
    __shared__ float s[T_];
    __shared__ float red[128];

    const size_t base = (size_t)(b * T_) * (3 * D_);
    const float* qrow = g_qkv + base + (size_t)qi * (3 * D_) + h * HD_;
    if (tid < HD_) qv[tid] = qrow[tid];
    __syncthreads();

    const int nk = qi + 1;
    const float scale = 0.125f;

    for (int k = tid; k < nk; k += 128) {
        const float* krow = g_qkv + base + (size_t)k * (3 * D_) + D_ + h * HD_;
        float acc = 0.f;
        #pragma unroll
        for (int d = 0; d < HD_; d += 4) {
            float4 k4 = *reinterpret_cast<const float4*>(krow + d);
            acc = fmaf(qv[d], k4.x, acc);
            acc = fmaf(qv[d + 1], k4.y, acc);
            acc = fmaf(qv[d + 2], k4.z, acc);
            acc = fmaf(qv[d + 3], k4.w, acc);
        }
        s[k] = acc * scale;
    }
    __syncthreads();

    float m = -INFINITY;
    for (int k = tid; k < nk; k += 128) m = fmaxf(m, s[k]);
    red[tid] = m; __syncthreads();
    for (int o = 64; o > 0; o >>= 1) {
        if (tid < o) red[tid] = fmaxf(red[tid], red[tid + o]);
        __syncthreads();
    }
    m = red[0]; __syncthreads();

    float sum = 0.f;
    for (int k = tid; k < nk; k += 128) {
        float e = expf(s[k] - m);
        s[k] = e;
        sum += e;
    }
    red[tid] = sum; __syncthreads();
    for (int o = 64; o > 0; o >>= 1) {
        if (tid < o) red[tid] += red[tid + o];
        __syncthreads();
    }
    float inv = 1.f / red[0];
    __syncthreads();

    if (tid < HD_) {
        const float* vcol = g_qkv + base + 2 * D_ + h * HD_ + tid;
        float o = 0.f;
        for (int k = 0; k < nk; k++)
            o = fmaf(s[k], vcol[(size_t)k * (3 * D_)], o);
        float val = o * inv;
        __half hh, ll; split_h(val, hh, ll);
        size_t oi = (size_t)(b * T_ + qi) * D_ + h * HD_ + tid;
        g_o_h[oi] = hh;
        g_o_l[oi] = ll;
    }
}

// ===========================================================================
// Host orchestration
// ===========================================================================
static inline dim3 tcg_grid(int N) {
    return dim3(NT_ / GBM, (N + GBN - 1) / GBN);
}

extern "C" void kernel_launch(void* const* d_in, const int* in_sizes, int n_in,
                              void* d_out, int out_size) {
    (void)in_sizes; (void)n_in; (void)out_size;
    const int*   idx    = (const int*)  d_in[0];
    const float* tok    = (const float*)d_in[1];
    const float* pos    = (const float*)d_in[2];
    const float* qkv_w  = (const float*)d_in[3];
    const float* qkv_b  = (const float*)d_in[4];
    const float* proj_w = (const float*)d_in[5];
    const float* proj_b = (const float*)d_in[6];
    const float* ff1_w  = (const float*)d_in[7];
    const float* ff1_b  = (const float*)d_in[8];
    const float* ff2_w  = (const float*)d_in[9];
    const float* ff2_b  = (const float*)d_in[10];
    const float* ln1_s  = (const float*)d_in[11];
    const float* ln1_b  = (const float*)d_in[12];
    const float* ln2_s  = (const float*)d_in[13];
    const float* ln2_b  = (const float*)d_in[14];
    const float* lnf_s  = (const float*)d_in[15];
    const float* lnf_b  = (const float*)d_in[16];
    float* out = (float*)d_out;

    float *px, *pqkv;
    __half *phh, *phl, *poh, *pol, *pffh, *pffl;
    __half *pqkvTh, *pqkvTl, *pprojTh, *pprojTl, *pff1Th, *pff1Tl, *pff2Th, *pff2Tl;
    __half *ptokh, *ptokl;
    cudaGetSymbolAddress((void**)&px,     g_x);
    cudaGetSymbolAddress((void**)&pqkv,   g_qkv);
    cudaGetSymbolAddress((void**)&phh,    g_h_h);
    cudaGetSymbolAddress((void**)&phl,    g_h_l);
    cudaGetSymbolAddress((void**)&poh,    g_o_h);
    cudaGetSymbolAddress((void**)&pol,    g_o_l);
    cudaGetSymbolAddress((void**)&pffh,   g_ff_h);
    cudaGetSymbolAddress((void**)&pffl,   g_ff_l);
    cudaGetSymbolAddress((void**)&pqkvTh, g_qkvT_h);
    cudaGetSymbolAddress((void**)&pqkvTl, g_qkvT_l);
    cudaGetSymbolAddress((void**)&pprojTh, g_projT_h);
    cudaGetSymbolAddress((void**)&pprojTl, g_projT_l);
    cudaGetSymbolAddress((void**)&pff1Th, g_ff1T_h);
    cudaGetSymbolAddress((void**)&pff1Tl, g_ff1T_l);
    cudaGetSymbolAddress((void**)&pff2Th, g_ff2T_h);
    cudaGetSymbolAddress((void**)&pff2Tl, g_ff2T_l);
    cudaGetSymbolAddress((void**)&ptokh,  g_tok_h);
    cudaGetSymbolAddress((void**)&ptokl,  g_tok_l);

    cudaFuncSetAttribute(mma_gemm<0>,
                         cudaFuncAttributeMaxDynamicSharedMemorySize, GEMM_SMEM);
    cudaFuncSetAttribute(mma_gemm<1>,
                         cudaFuncAttributeMaxDynamicSharedMemorySize, GEMM_SMEM);

    // Pre-split tok_emb, pre-transpose+split weights
    tok_split<<<(V_ * D_) / (256 * 4), 256>>>(tok);
    dim3 tb(32, 8);
    for (int l = 0; l < L_; l++) {
        transpose_split<<<dim3(3 * D_ / 32, D_ / 32), tb>>>(
            qkv_w + (size_t)l * D_ * 3 * D_,
            pqkvTh + (size_t)l * 3 * D_ * D_, pqkvTl + (size_t)l * 3 * D_ * D_,
            D_, 3 * D_);
        transpose_split<<<dim3(D_ / 32, D_ / 32), tb>>>(
            proj_w + (size_t)l * D_ * D_,
            pprojTh + (size_t)l * D_ * D_, pprojTl + (size_t)l * D_ * D_,
            D_, D_);
        transpose_split<<<dim3(4 * D_ / 32, D_ / 32), tb>>>(
            ff1_w + (size_t)l * D_ * 4 * D_,
            pff1Th + (size_t)l * 4 * D_ * D_, pff1Tl + (size_t)l * 4 * D_ * D_,
            D_, 4 * D_);
        transpose_split<<<dim3(D_ / 32, 4 * D_ / 32), tb>>>(
            ff2_w + (size_t)l * 4 * D_ * D_,
            pff2Th + (size_t)l * D_ * 4 * D_, pff2Tl + (size_t)l * D_ * 4 * D_,
            4 * D_, D_);
    }

    embed_kernel<<<NT_, 256>>>(idx, tok, pos);

    for (int l = 0; l < L_; l++) {
        ln_split_kernel<<<NT_, 256>>>(px, phh, phl,
                                      ln1_s + (size_t)l * D_, ln1_b + (size_t)l * D_);
        // qkv = h @ qkv_w + qkv_b
        mma_gemm<0><<<tcg_grid(3 * D_), 256, GEMM_SMEM>>>(
            phh, phl,
            pqkvTh + (size_t)l * 3 * D_ * D_, pqkvTl + (size_t)l * 3 * D_ * D_,
            qkv_b + (size_t)l * 3 * D_, nullptr, pqkv, nullptr, nullptr,
            3 * D_, D_);
        attn_kernel<<<B_ * H_ * T_, 128>>>();
        // x = x + o @ proj_w + proj_b
        mma_gemm<0><<<tcg_grid(D_), 256, GEMM_SMEM>>>(
            poh, pol,
            pprojTh + (size_t)l * D_ * D_, pprojTl + (size_t)l * D_ * D_,
            proj_b + (size_t)l * D_, px, px, nullptr, nullptr,
            D_, D_);
        ln_split_kernel<<<NT_, 256>>>(px, phh, phl,
                                      ln2_s + (size_t)l * D_, ln2_b + (size_t)l * D_);
        // ff = gelu(h @ ff1_w + ff1_b)  -> split halves
        mma_gemm<1><<<tcg_grid(4 * D_), 256, GEMM_SMEM>>>(
            phh, phl,
            pff1Th + (size_t)l * 4 * D_ * D_, pff1Tl + (size_t)l * 4 * D_ * D_,
            ff1_b + (size_t)l * 4 * D_, nullptr, nullptr, pffh, pffl,
            4 * D_, D_);
        // x = x + ff @ ff2_w + ff2_b
        mma_gemm<0><<<tcg_grid(D_), 256, GEMM_SMEM>>>(
            pffh, pffl,
            pff2Th + (size_t)l * D_ * 4 * D_, pff2Tl + (size_t)l * D_ * 4 * D_,
            ff2_b + (size_t)l * D_, px, px, nullptr, nullptr,
            D_, 4 * D_);
    }

    ln_split_kernel<<<NT_, 256>>>(px, phh, phl, lnf_s, lnf_b);
    // logits = h @ tok_emb^T  (tok pre-split, [V,D] K-contiguous)
    mma_gemm<0><<<tcg_grid(V_), 256, GEMM_SMEM>>>(
        phh, phl, ptokh, ptokl, nullptr, nullptr, out, nullptr, nullptr,
        V_, D_);
}